// round 6
// baseline (speedup 1.0000x reference)
#include <cuda_runtime.h>
#include <math.h>

#define NN 50000
#define NE 500000
#define FN 7
#define FE 8
#define DD 64
#define HH 128
#define PP 256           // Pab width (src-part 128 | dst-part 128)
#define EIN 136
#define UIN 192
#define LL 3
#define EPB 64           // edges per block-iteration (msg/pred)

typedef unsigned long long u64;

__device__ __forceinline__ void ffma2(u64 &d, u64 a, u64 b) {
    asm("fma.rn.f32x2 %0, %1, %2, %0;" : "+l"(d) : "l"(a), "l"(b));
}
__device__ __forceinline__ float f2sum(u64 a) {
    float lo, hi;
    asm("mov.b64 {%0, %1}, %2;" : "=f"(lo), "=f"(hi) : "l"(a));
    return lo + hi;
}
__device__ __forceinline__ void red_add_v4(float* p, float4 v) {
    u64 gp;
    asm("cvta.to.global.u64 %0, %1;" : "=l"(gp) : "l"(p));
    asm volatile("red.global.add.v4.f32 [%0], {%1, %2, %3, %4};"
                 :: "l"(gp), "f"(v.x), "f"(v.y), "f"(v.z), "f"(v.w) : "memory");
}
__device__ __forceinline__ void cp16(unsigned saddr, const void* g) {
    asm volatile("cp.async.cg.shared.global [%0], [%1], 16;" :: "r"(saddr), "l"(g));
}
#define CP_COMMIT()   asm volatile("cp.async.commit_group;" ::: "memory")
#define CP_WAIT_ALL() asm volatile("cp.async.wait_group 0;" ::: "memory")

// ---------------- scratch ----------------
__device__ float g_x[NN * DD];
__device__ float g_agg[NN * HH];
__device__ float g_cnt[NN];
__device__ float g_pab[NN * PP];

// ---------------- init ----------------
__global__ void init_kernel() {
    int i = blockIdx.x * blockDim.x + threadIdx.x;
    const int A4 = NN * HH / 4;
    if (i < A4) ((float4*)g_agg)[i] = make_float4(0.f, 0.f, 0.f, 0.f);
    else if (i < A4 + NN / 4) ((float4*)g_cnt)[i - A4] = make_float4(0.f, 0.f, 0.f, 0.f);
}

__global__ void count_kernel(const int* __restrict__ dst) {
    int e = blockIdx.x * blockDim.x + threadIdx.x;
    if (e < NE) atomicAdd(&g_cnt[dst[e]], 1.0f);
}

// ---------------- fused embed + node_lin(layer0) ----------------
#define NLS 68
#define EMB_SMEM ((PP*NLS + FN*DD + DD + 8*FN + 8*DD) * 4)

__global__ void __launch_bounds__(256, 2)
embed_nl_kernel(const float* __restrict__ nf,
                const float* __restrict__ eW, const float* __restrict__ eb,
                const float* __restrict__ W1) {
    extern __shared__ float s[];
    float* sWt = s;                    // [256][68]
    float* sWe = sWt + PP * NLS;
    float* sBe = sWe + FN * DD;
    float* sNf = sBe + DD;
    float* sX  = sNf + 8 * FN;

    const int tid = threadIdx.x;
    for (int i = tid; i < DD * PP; i += 256) {
        int k = i >> 8, j = i & 255;
        sWt[j * NLS + k] = (j < HH) ? W1[k * HH + j] : W1[(DD + k) * HH + (j - HH)];
    }
    for (int i = tid; i < FN * DD; i += 256) sWe[i] = eW[i];
    if (tid < DD) sBe[tid] = eb[tid];
    __syncthreads();

    const int step = gridDim.x * 8;
    for (int n0 = blockIdx.x * 8; n0 < NN; n0 += step) {
        for (int i = tid; i < 8 * FN; i += 256) {
            int c = i / FN, f = i % FN;
            sNf[i] = nf[(n0 + c) * FN + f];
        }
        __syncthreads();
        for (int i = tid; i < 8 * DD; i += 256) {
            int c = i >> 6, d = i & 63;
            float xv = sBe[d];
#pragma unroll
            for (int f = 0; f < FN; f++) xv += sNf[c * FN + f] * sWe[f * DD + d];
            xv = fmaxf(xv, 0.f);
            sX[c * DD + d] = xv;
            g_x[(n0 + c) * DD + d] = xv;
        }
        __syncthreads();
        u64 acc[8];
#pragma unroll
        for (int c = 0; c < 8; c++) acc[c] = 0ull;
        const float* wr = sWt + tid * NLS;
#pragma unroll 4
        for (int k = 0; k < DD; k += 4) {
            ulonglong2 w = *(const ulonglong2*)(wr + k);
#pragma unroll
            for (int c = 0; c < 8; c++) {
                ulonglong2 v = *(const ulonglong2*)(sX + c * DD + k);
                ffma2(acc[c], w.x, v.x);
                ffma2(acc[c], w.y, v.y);
            }
        }
#pragma unroll
        for (int c = 0; c < 8; c++)
            g_pab[(size_t)(n0 + c) * PP + tid] = f2sum(acc[c]);
        __syncthreads();
    }
}

// ---------------- node_lin ----------------
#define NL_SMEM ((PP*NLS + 8*DD) * 4)

__global__ void __launch_bounds__(256, 2)
node_lin_kernel(const float* __restrict__ W1) {
    extern __shared__ float s[];
    float* sWt = s;
    float* sX  = sWt + PP * NLS;

    const int tid = threadIdx.x;
    for (int i = tid; i < DD * PP; i += 256) {
        int k = i >> 8, j = i & 255;
        sWt[j * NLS + k] = (j < HH) ? W1[k * HH + j] : W1[(DD + k) * HH + (j - HH)];
    }
    __syncthreads();

    const int step = gridDim.x * 8;
    for (int n0 = blockIdx.x * 8; n0 < NN; n0 += step) {
        for (int i = tid; i < 8 * DD; i += 256) {
            int c = i >> 6, k = i & 63;
            sX[i] = g_x[(n0 + c) * DD + k];
        }
        __syncthreads();
        u64 acc[8];
#pragma unroll
        for (int c = 0; c < 8; c++) acc[c] = 0ull;
        const float* wr = sWt + tid * NLS;
#pragma unroll 4
        for (int k = 0; k < DD; k += 4) {
            ulonglong2 w = *(const ulonglong2*)(wr + k);
#pragma unroll
            for (int c = 0; c < 8; c++) {
                ulonglong2 v = *(const ulonglong2*)(sX + c * DD + k);
                ffma2(acc[c], w.x, v.x);
                ffma2(acc[c], w.y, v.y);
            }
        }
#pragma unroll
        for (int c = 0; c < 8; c++)
            g_pab[(size_t)(n0 + c) * PP + tid] = f2sum(acc[c]);
        __syncthreads();
    }
}

// ---------------- fused edge message (1024 thr, cp.async staging) ----------------
#define W2S 132
#define MSG_SMEM ((HH*W2S + 2*HH + EPB*HH + EPB*HH + EPB*PP + EPB*FE) * 4)

__global__ void __launch_bounds__(1024, 1)
msg_kernel(const float* __restrict__ ea,
           const int* __restrict__ src, const int* __restrict__ dst,
           const float* __restrict__ W1, const float* __restrict__ b1,
           const float* __restrict__ W2, const float* __restrict__ b2) {
    extern __shared__ float s[];
    float* sW2t = s;                       // [128][132]
    float* sB1  = sW2t + HH * W2S;
    float* sB2  = sB1 + HH;
    float* sH   = sB2 + HH;                // [64][128]
    float* sMsg = sH + EPB * HH;           // [64][128]
    float* sPab = sMsg + EPB * HH;         // [64][256]
    float* sEa  = sPab + EPB * PP;         // [64][8]

    const unsigned aPab = (unsigned)__cvta_generic_to_shared(sPab);
    const unsigned aEa  = (unsigned)__cvta_generic_to_shared(sEa);

    const int tid = threadIdx.x;
    for (int i = tid; i < HH * HH; i += 1024) { int k = i >> 7, j = i & 127; sW2t[j * W2S + k] = W2[i]; }
    if (tid < HH) { sB1[tid] = b1[tid]; sB2[tid] = b2[tid]; }

    const int j = tid & 127, g = tid >> 7;       // phaseA: 8 edges/thread
    const int j2 = tid & 63, eg = tid >> 6;      // GEMM2: E4 x C2
    const int wid = tid >> 5, lane = tid & 31;
    const float b1v = b1[j];
    const float b2lo = b2[j2], b2hi = b2[j2 + 64];
    float w1c[8];
#pragma unroll
    for (int f = 0; f < 8; f++) w1c[f] = W1[(2 * DD + f) * HH + j];

    int nsrc[2], ndst[2], pd_cur[2];

#define MSG_LOADIDX(BASE) { \
    _Pragma("unroll") \
    for (int t = 0; t < 2; t++) { \
        int ge = (BASE) + wid * 2 + t; \
        int gc = (ge < NE) ? ge : NE - 1; \
        nsrc[t] = src[gc]; ndst[t] = dst[gc]; } }

#define MSG_STAGE(BASE) { \
    _Pragma("unroll") \
    for (int t = 0; t < 2; t++) { \
        int le = wid * 2 + t; \
        cp16(aPab + (le * PP + lane * 4) * 4, g_pab + (size_t)nsrc[t] * PP + lane * 4); \
        cp16(aPab + (le * PP + HH + lane * 4) * 4, g_pab + (size_t)ndst[t] * PP + HH + lane * 4); \
        if (lane < 2) { \
            int ge = (BASE) + le; \
            int gc = (ge < NE) ? ge : NE - 1; \
            cp16(aEa + (le * FE + lane * 4) * 4, ea + (size_t)gc * FE + lane * 4); } } }

    int e0 = blockIdx.x * EPB;
    const int step = gridDim.x * EPB;
    MSG_LOADIDX(e0);
    MSG_STAGE(e0);
    CP_COMMIT();

    for (; e0 < NE; e0 += step) {
        int enext = e0 + step;
        CP_WAIT_ALL();
        __syncthreads();                         // staged tile visible

        // dst ids for this tile (regs), then prefetch indices for next
#pragma unroll
        for (int t = 0; t < 2; t++) pd_cur[t] = ndst[t];
        if (enext < NE) MSG_LOADIDX(enext);

        // ---- phase A: h = relu(Pa + Pb + ea@W1c + b1) : 8 edges/thread ----
#pragma unroll
        for (int c = 0; c < 8; c++) {
            int e = g + 8 * c;
            float hv = sPab[e * PP + j] + sPab[e * PP + HH + j] + b1v;
            float4 a0 = ((const float4*)(sEa + e * FE))[0];
            float4 a1 = ((const float4*)(sEa + e * FE))[1];
            hv = fmaf(a0.x, w1c[0], hv); hv = fmaf(a0.y, w1c[1], hv);
            hv = fmaf(a0.z, w1c[2], hv); hv = fmaf(a0.w, w1c[3], hv);
            hv = fmaf(a1.x, w1c[4], hv); hv = fmaf(a1.y, w1c[5], hv);
            hv = fmaf(a1.z, w1c[6], hv); hv = fmaf(a1.w, w1c[7], hv);
            sH[e * HH + j] = fmaxf(hv, 0.f);
        }
        __syncthreads();                         // sH visible; sPab/sEa free

        // async staging of next tile lands under GEMM2 + scatter
        if (enext < NE) MSG_STAGE(enext);
        CP_COMMIT();

        // ---- GEMM2: E=4 edges x C=2 channels per thread ----
        u64 aLo[4], aHi[4];
#pragma unroll
        for (int c = 0; c < 4; c++) { aLo[c] = 0ull; aHi[c] = 0ull; }
        const float* wr0 = sW2t + j2 * W2S;
        const float* wr1 = sW2t + (j2 + 64) * W2S;
#pragma unroll 2
        for (int k = 0; k < HH; k += 4) {
            ulonglong2 w0 = *(const ulonglong2*)(wr0 + k);
            ulonglong2 w1 = *(const ulonglong2*)(wr1 + k);
#pragma unroll
            for (int c = 0; c < 4; c++) {
                ulonglong2 v = *(const ulonglong2*)(sH + (eg * 4 + c) * HH + k);
                ffma2(aLo[c], w0.x, v.x);
                ffma2(aLo[c], w0.y, v.y);
                ffma2(aHi[c], w1.x, v.x);
                ffma2(aHi[c], w1.y, v.y);
            }
        }
#pragma unroll
        for (int c = 0; c < 4; c++) {
            int e = eg * 4 + c;
            sMsg[e * HH + j2]      = f2sum(aLo[c]) + b2lo;
            sMsg[e * HH + 64 + j2] = f2sum(aHi[c]) + b2hi;
        }
        __syncthreads();                         // sMsg visible

        // ---- scatter: warp -> its 2 edges ----
#pragma unroll
        for (int t = 0; t < 2; t++) {
            int le = wid * 2 + t;
            if (e0 + le < NE) {
                float4 m = ((const float4*)(sMsg + le * HH))[lane];
                red_add_v4(g_agg + (size_t)pd_cur[t] * HH + lane * 4, m);
            }
        }
    }
#undef MSG_LOADIDX
#undef MSG_STAGE
}

// ---------------- node update + LayerNorm + fused agg-zero ----------------
#define WUS 196
#define UPD_SMEM ((DD*WUS + 3*DD + 8*UIN + 32) * 4)

__global__ void __launch_bounds__(256, 2)
upd_kernel(const float* __restrict__ W, const float* __restrict__ b,
           const float* __restrict__ lg, const float* __restrict__ lb) {
    extern __shared__ float s[];
    float* sWt  = s;
    float* sB   = sWt + DD * WUS;
    float* sG   = sB + DD;
    float* sLB  = sG + DD;
    float* sNin = sLB + DD;
    float* sRed = sNin + 8 * UIN;

    const int tid = threadIdx.x;
    for (int i = tid; i < UIN * DD; i += 256) { int k = i >> 6, d = i & 63; sWt[d * WUS + k] = W[i]; }
    if (tid < DD) { sB[tid] = b[tid]; sG[tid] = lg[tid]; sLB[tid] = lb[tid]; }
    __syncthreads();

    const int d = tid & 63;
    const int g = tid >> 6;
    const int wg = (tid >> 5) & 1;
    const int wid = tid >> 5, lane = tid & 31;
    const float bv = sB[d], gv = sG[d], lbv = sLB[d];

    for (int n0 = blockIdx.x * 8; n0 < NN; n0 += gridDim.x * 8) {
        {
            int n = n0 + wid;
            if (n < NN) {
                float inv = 1.f / (g_cnt[n] + 1e-6f);
                for (int i = lane; i < UIN; i += 32) {
                    float v = (i < DD) ? g_x[n * DD + i] : g_agg[n * HH + (i - DD)] * inv;
                    sNin[wid * UIN + i] = v;
                }
            }
        }
        __syncthreads();
        {
            int n = n0 + wid;
            if (n < NN) ((float4*)(g_agg + (size_t)n * HH))[lane] = make_float4(0.f, 0.f, 0.f, 0.f);
        }

        float outv[2];
        {
            u64 a0 = 0ull, a1 = 0ull;
            const float* wr = sWt + d * WUS;
            const float* in0 = sNin + g * UIN;
            const float* in1 = sNin + (g + 4) * UIN;
#pragma unroll 4
            for (int k = 0; k < UIN; k += 4) {
                ulonglong2 w = *(const ulonglong2*)(wr + k);
                ulonglong2 v0 = *(const ulonglong2*)(in0 + k);
                ulonglong2 v1 = *(const ulonglong2*)(in1 + k);
                ffma2(a0, w.x, v0.x); ffma2(a0, w.y, v0.y);
                ffma2(a1, w.x, v1.x); ffma2(a1, w.y, v1.y);
            }
            outv[0] = in0[d] + fmaxf(f2sum(a0) + bv, 0.f);
            outv[1] = in1[d] + fmaxf(f2sum(a1) + bv, 0.f);
        }
#pragma unroll
        for (int c = 0; c < 2; c++) {
            int ln = g + 4 * c;
            float s1 = outv[c], s2 = outv[c] * outv[c];
#pragma unroll
            for (int off = 16; off; off >>= 1) {
                s1 += __shfl_xor_sync(0xFFFFFFFFu, s1, off);
                s2 += __shfl_xor_sync(0xFFFFFFFFu, s2, off);
            }
            if (lane == 0) { sRed[(ln * 2 + wg) * 2] = s1; sRed[(ln * 2 + wg) * 2 + 1] = s2; }
        }
        __syncthreads();
#pragma unroll
        for (int c = 0; c < 2; c++) {
            int ln = g + 4 * c;
            int n = n0 + ln;
            if (n < NN) {
                float s1 = sRed[(ln * 2) * 2] + sRed[(ln * 2 + 1) * 2];
                float s2 = sRed[(ln * 2) * 2 + 1] + sRed[(ln * 2 + 1) * 2 + 1];
                float mu = s1 * (1.f / DD);
                float var = s2 * (1.f / DD) - mu * mu;
                g_x[n * DD + d] = (outv[c] - mu) * rsqrtf(var + 1e-5f) * gv + lbv;
            }
        }
        __syncthreads();
    }
}

// ---------------- edge predictor (1024 thr, cp.async staging) ----------------
#define PRED_SMEM ((DD*W2S + DD + HH + DD + EPB*HH + EPB*DD + EPB*PP + EPB*FE) * 4)

__global__ void __launch_bounds__(1024, 1)
pred_kernel(const float* __restrict__ ea,
            const int* __restrict__ src, const int* __restrict__ dst,
            const float* __restrict__ W1, const float* __restrict__ b1,
            const float* __restrict__ W2, const float* __restrict__ b2,
            const float* __restrict__ W3, const float* __restrict__ b3,
            float* __restrict__ out) {
    extern __shared__ float s[];
    float* sW2t = s;                   // [64][132]
    float* sW3  = sW2t + DD * W2S;
    float* sB1  = sW3 + DD;
    float* sB2  = sB1 + HH;
    float* sH1  = sB2 + DD;            // [64][128]
    float* sH2  = sH1 + EPB * HH;      // [64][64]
    float* sPab = sH2 + EPB * DD;      // [64][256]
    float* sEa  = sPab + EPB * PP;     // [64][8]

    const unsigned aPab = (unsigned)__cvta_generic_to_shared(sPab);
    const unsigned aEa  = (unsigned)__cvta_generic_to_shared(sEa);

    const int tid = threadIdx.x;
    for (int i = tid; i < HH * DD; i += 1024) { int k = i >> 6, jj = i & 63; sW2t[jj * W2S + k] = W2[i]; }
    if (tid < DD) sW3[tid] = W3[tid];
    if (tid < HH) sB1[tid] = b1[tid];
    if (tid < DD) sB2[tid] = b2[tid];

    const int j = tid & 127, g = tid >> 7;
    const int j2 = tid & 63, eg = tid >> 6;
    const int wid = tid >> 5, lane = tid & 31;
    const float b1v = b1[j], b2v = b2[j2], b3v = b3[0];
    float w1c[8];
#pragma unroll
    for (int f = 0; f < 8; f++) w1c[f] = W1[(2 * DD + f) * HH + j];

    int nsrc[2], ndst[2];

#define PRD_LOADIDX(BASE) { \
    _Pragma("unroll") \
    for (int t = 0; t < 2; t++) { \
        int ge = (BASE) + wid * 2 + t; \
        int gc = (ge < NE) ? ge : NE - 1; \
        nsrc[t] = src[gc]; ndst[t] = dst[gc]; } }

#define PRD_STAGE(BASE) { \
    _Pragma("unroll") \
    for (int t = 0; t < 2; t++) { \
        int le = wid * 2 + t; \
        cp16(aPab + (le * PP + lane * 4) * 4, g_pab + (size_t)nsrc[t] * PP + lane * 4); \
        cp16(aPab + (le * PP + HH + lane * 4) * 4, g_pab + (size_t)ndst[t] * PP + HH + lane * 4); \
        if (lane < 2) { \
            int ge = (BASE) + le; \
            int gc = (ge < NE) ? ge : NE - 1; \
            cp16(aEa + (le * FE + lane * 4) * 4, ea + (size_t)gc * FE + lane * 4); } } }

    int e0 = blockIdx.x * EPB;
    const int step = gridDim.x * EPB;
    PRD_LOADIDX(e0);
    PRD_STAGE(e0);
    CP_COMMIT();

    for (; e0 < NE; e0 += step) {
        int enext = e0 + step;
        CP_WAIT_ALL();
        __syncthreads();

        if (enext < NE) PRD_LOADIDX(enext);

        // phase A: h1 = relu(Pa + Pb + ea@W1c + b1)
#pragma unroll
        for (int c = 0; c < 8; c++) {
            int e = g + 8 * c;
            float hv = sPab[e * PP + j] + sPab[e * PP + HH + j] + b1v;
            float4 a0 = ((const float4*)(sEa + e * FE))[0];
            float4 a1 = ((const float4*)(sEa + e * FE))[1];
            hv = fmaf(a0.x, w1c[0], hv); hv = fmaf(a0.y, w1c[1], hv);
            hv = fmaf(a0.z, w1c[2], hv); hv = fmaf(a0.w, w1c[3], hv);
            hv = fmaf(a1.x, w1c[4], hv); hv = fmaf(a1.y, w1c[5], hv);
            hv = fmaf(a1.z, w1c[6], hv); hv = fmaf(a1.w, w1c[7], hv);
            sH1[e * HH + j] = fmaxf(hv, 0.f);
        }
        __syncthreads();

        if (enext < NE) PRD_STAGE(enext);
        CP_COMMIT();

        // GEMM2: 128 -> 64, E=4 C=1
        u64 acc[4];
#pragma unroll
        for (int c = 0; c < 4; c++) acc[c] = 0ull;
        const float* wr = sW2t + j2 * W2S;
#pragma unroll 2
        for (int k = 0; k < HH; k += 4) {
            ulonglong2 w = *(const ulonglong2*)(wr + k);
#pragma unroll
            for (int c = 0; c < 4; c++) {
                ulonglong2 v = *(const ulonglong2*)(sH1 + (eg * 4 + c) * HH + k);
                ffma2(acc[c], w.x, v.x);
                ffma2(acc[c], w.y, v.y);
            }
        }
#pragma unroll
        for (int c = 0; c < 4; c++)
            sH2[(eg * 4 + c) * DD + j2] = fmaxf(f2sum(acc[c]) + b2v, 0.f);
        __syncthreads();

        // final dot 64 -> 1 + tanh : warp -> its 2 edges
#pragma unroll
        for (int t = 0; t < 2; t++) {
            int le = wid * 2 + t, ge = e0 + le;
            float v = sH2[le * DD + lane] * sW3[lane]
                    + sH2[le * DD + 32 + lane] * sW3[32 + lane];
#pragma unroll
            for (int off = 16; off; off >>= 1) v += __shfl_xor_sync(0xFFFFFFFFu, v, off);
            if (lane == 0 && ge < NE) out[ge] = tanhf(v + b3v);
        }
    }
#undef PRD_LOADIDX
#undef PRD_STAGE
}

// ---------------- launch ----------------
extern "C" void kernel_launch(void* const* d_in, const int* in_sizes, int n_in,
                              void* d_out, int out_size) {
    const float* node_features = (const float*)d_in[0];
    const float* edge_attr     = (const float*)d_in[1];
    const float* embed_W       = (const float*)d_in[2];
    const float* embed_b       = (const float*)d_in[3];
    const float* msg_W1        = (const float*)d_in[4];
    const float* msg_b1        = (const float*)d_in[5];
    const float* msg_W2        = (const float*)d_in[6];
    const float* msg_b2        = (const float*)d_in[7];
    const float* upd_W         = (const float*)d_in[8];
    const float* upd_b         = (const float*)d_in[9];
    const float* ln_g          = (const float*)d_in[10];
    const float* ln_b          = (const float*)d_in[11];
    const float* pred_W1       = (const float*)d_in[12];
    const float* pred_b1       = (const float*)d_in[13];
    const float* pred_W2       = (const float*)d_in[14];
    const float* pred_b2       = (const float*)d_in[15];
    const float* pred_W3       = (const float*)d_in[16];
    const float* pred_b3       = (const float*)d_in[17];
    const int*   edge_index    = (const int*)d_in[18];
    float* out = (float*)d_out;

    const int* src = edge_index;
    const int* dst = edge_index + NE;

    cudaFuncSetAttribute(msg_kernel,      cudaFuncAttributeMaxDynamicSharedMemorySize, MSG_SMEM);
    cudaFuncSetAttribute(pred_kernel,     cudaFuncAttributeMaxDynamicSharedMemorySize, PRED_SMEM);
    cudaFuncSetAttribute(upd_kernel,      cudaFuncAttributeMaxDynamicSharedMemorySize, UPD_SMEM);
    cudaFuncSetAttribute(node_lin_kernel, cudaFuncAttributeMaxDynamicSharedMemorySize, NL_SMEM);
    cudaFuncSetAttribute(embed_nl_kernel, cudaFuncAttributeMaxDynamicSharedMemorySize, EMB_SMEM);

    init_kernel<<<(NN * HH / 4 + NN / 4 + 255) / 256, 256>>>();
    count_kernel<<<(NE + 255) / 256, 256>>>(dst);
    embed_nl_kernel<<<296, 256, EMB_SMEM>>>(node_features, embed_W, embed_b, msg_W1);

    for (int l = 0; l < LL; l++) {
        // launch index 3 on l=0 -> ncu profiles msg_kernel
        msg_kernel<<<148, 1024, MSG_SMEM>>>(edge_attr, src, dst,
                                            msg_W1 + l * EIN * HH, msg_b1 + l * HH,
                                            msg_W2 + l * HH * HH, msg_b2 + l * HH);
        upd_kernel<<<296, 256, UPD_SMEM>>>(upd_W + l * UIN * DD, upd_b + l * DD,
                                           ln_g + l * DD, ln_b + l * DD);
        const float* nextW1 = (l < LL - 1) ? (msg_W1 + (l + 1) * EIN * HH) : pred_W1;
        node_lin_kernel<<<296, 256, NL_SMEM>>>(nextW1);
    }

    pred_kernel<<<148, 1024, PRED_SMEM>>>(edge_attr, src, dst,
                                          pred_W1, pred_b1, pred_W2, pred_b2,
                                          pred_W3, pred_b3, out);
}